// round 7
// baseline (speedup 1.0000x reference)
#include <cuda_runtime.h>
#include <cuda_bf16.h>

// out[b,t,v] = sum_d x[b,t,d,v] * w[d] + bias
// x: (B=2, T=512, D=8, V=32000) fp32 ; w: (8,) ; b: (1,)
// v5: best structure (1 float4/thread, 8 front-batched LDG.128, 256-thr
// blocks, regs=32) + weights/bias in __constant__ memory (staged via
// async D2D memcpy-to-symbol, graph-capturable). CTA prologue is now pure
// DRAM loads -> requests reach HBM earlier, no per-thread w/bias LDGs.

#define BT    1024      // B*T
#define DEPTH 8
#define V     32000
#define V4    (V / 4)   // 8000 float4 per (b,t,d) row
#define NTHR  256

__constant__ float c_w[DEPTH];
__constant__ float c_bias;

__global__ __launch_bounds__(NTHR) void tokentree_kernel(
    const float4* __restrict__ x,   // (BT, DEPTH, V4)
    float4*       __restrict__ out) // (BT, V4)
{
    const int v4 = blockIdx.x * NTHR + threadIdx.x;
    if (v4 >= V4) return;
    const int bt = blockIdx.y;

    const float4* xp = x + (size_t)bt * DEPTH * V4 + v4;

    // 8 independent coalesced 128B-per-warp DRAM loads, front-batched.
    // No other memory ops precede these -> earliest possible HBM requests.
    float4 x0 = __ldcg(xp + 0 * V4);
    float4 x1 = __ldcg(xp + 1 * V4);
    float4 x2 = __ldcg(xp + 2 * V4);
    float4 x3 = __ldcg(xp + 3 * V4);
    float4 x4 = __ldcg(xp + 4 * V4);
    float4 x5 = __ldcg(xp + 5 * V4);
    float4 x6 = __ldcg(xp + 6 * V4);
    float4 x7 = __ldcg(xp + 7 * V4);

    const float b0 = c_bias;
    float4 acc;
    acc.x = b0; acc.y = b0; acc.z = b0; acc.w = b0;

    acc.x = fmaf(c_w[0], x0.x, acc.x); acc.y = fmaf(c_w[0], x0.y, acc.y);
    acc.z = fmaf(c_w[0], x0.z, acc.z); acc.w = fmaf(c_w[0], x0.w, acc.w);
    acc.x = fmaf(c_w[1], x1.x, acc.x); acc.y = fmaf(c_w[1], x1.y, acc.y);
    acc.z = fmaf(c_w[1], x1.z, acc.z); acc.w = fmaf(c_w[1], x1.w, acc.w);
    acc.x = fmaf(c_w[2], x2.x, acc.x); acc.y = fmaf(c_w[2], x2.y, acc.y);
    acc.z = fmaf(c_w[2], x2.z, acc.z); acc.w = fmaf(c_w[2], x2.w, acc.w);
    acc.x = fmaf(c_w[3], x3.x, acc.x); acc.y = fmaf(c_w[3], x3.y, acc.y);
    acc.z = fmaf(c_w[3], x3.z, acc.z); acc.w = fmaf(c_w[3], x3.w, acc.w);
    acc.x = fmaf(c_w[4], x4.x, acc.x); acc.y = fmaf(c_w[4], x4.y, acc.y);
    acc.z = fmaf(c_w[4], x4.z, acc.z); acc.w = fmaf(c_w[4], x4.w, acc.w);
    acc.x = fmaf(c_w[5], x5.x, acc.x); acc.y = fmaf(c_w[5], x5.y, acc.y);
    acc.z = fmaf(c_w[5], x5.z, acc.z); acc.w = fmaf(c_w[5], x5.w, acc.w);
    acc.x = fmaf(c_w[6], x6.x, acc.x); acc.y = fmaf(c_w[6], x6.y, acc.y);
    acc.z = fmaf(c_w[6], x6.z, acc.z); acc.w = fmaf(c_w[6], x6.w, acc.w);
    acc.x = fmaf(c_w[7], x7.x, acc.x); acc.y = fmaf(c_w[7], x7.y, acc.y);
    acc.z = fmaf(c_w[7], x7.z, acc.z); acc.w = fmaf(c_w[7], x7.w, acc.w);

    out[(size_t)bt * V4 + v4] = acc;
}

extern "C" void kernel_launch(void* const* d_in, const int* in_sizes, int n_in,
                              void* d_out, int out_size) {
    const float4* x    = (const float4*)d_in[0];
    const float*  w    = (const float*)d_in[1];
    const float*  bias = (const float*)d_in[2];
    float4*       out  = (float4*)d_out;

    // Stage weights/bias into __constant__ memory. Async D2D memcpy ->
    // graph-capturable memcpy nodes; no allocation, deterministic.
    cudaMemcpyToSymbolAsync(c_w, w, DEPTH * sizeof(float), 0,
                            cudaMemcpyDeviceToDevice, 0);
    cudaMemcpyToSymbolAsync(c_bias, bias, sizeof(float), 0,
                            cudaMemcpyDeviceToDevice, 0);

    dim3 block(NTHR);
    dim3 grid((V4 + NTHR - 1) / NTHR, BT);   // (32, 1024)
    tokentree_kernel<<<grid, block>>>(x, out);
}

// round 8
// speedup vs baseline: 1.0253x; 1.0253x over previous
#include <cuda_runtime.h>
#include <cuda_bf16.h>

// out[b,t,v] = sum_d x[b,t,d,v] * w[d] + bias
// x: (B=2, T=512, D=8, V=32000) fp32 ; w: (8,) ; b: (1,)
// v6: exact v1 structure (best measured) + write-through stores (__stwt):
// writes stream to DRAM in combined bursts instead of lazy L2 dirty
// evictions interleaved with the read-fill stream.

#define BT    1024      // B*T
#define DEPTH 8
#define V     32000
#define V4    (V / 4)   // 8000 float4 per (b,t,d) row
#define NTHR  256

__global__ __launch_bounds__(NTHR) void tokentree_kernel(
    const float4* __restrict__ x,   // (BT, DEPTH, V4)
    const float*  __restrict__ w,   // (DEPTH,)
    const float*  __restrict__ bias,// (1,)
    float4*       __restrict__ out) // (BT, V4)
{
    const int v4 = blockIdx.x * NTHR + threadIdx.x;
    if (v4 >= V4) return;
    const int bt = blockIdx.y;

    // Weights + bias: tiny, L1-resident after first warp.
    float w0 = __ldg(&w[0]), w1 = __ldg(&w[1]), w2 = __ldg(&w[2]), w3 = __ldg(&w[3]);
    float w4 = __ldg(&w[4]), w5 = __ldg(&w[5]), w6 = __ldg(&w[6]), w7 = __ldg(&w[7]);
    float b0 = __ldg(&bias[0]);

    const float4* xp = x + (size_t)bt * DEPTH * V4 + v4;

    // 8 independent coalesced 128B-per-warp loads, front-batched -> MLP=8.
    float4 x0 = __ldg(xp + 0 * V4);
    float4 x1 = __ldg(xp + 1 * V4);
    float4 x2 = __ldg(xp + 2 * V4);
    float4 x3 = __ldg(xp + 3 * V4);
    float4 x4 = __ldg(xp + 4 * V4);
    float4 x5 = __ldg(xp + 5 * V4);
    float4 x6 = __ldg(xp + 6 * V4);
    float4 x7 = __ldg(xp + 7 * V4);

    float4 acc;
    acc.x = b0; acc.y = b0; acc.z = b0; acc.w = b0;

    acc.x = fmaf(w0, x0.x, acc.x); acc.y = fmaf(w0, x0.y, acc.y);
    acc.z = fmaf(w0, x0.z, acc.z); acc.w = fmaf(w0, x0.w, acc.w);
    acc.x = fmaf(w1, x1.x, acc.x); acc.y = fmaf(w1, x1.y, acc.y);
    acc.z = fmaf(w1, x1.z, acc.z); acc.w = fmaf(w1, x1.w, acc.w);
    acc.x = fmaf(w2, x2.x, acc.x); acc.y = fmaf(w2, x2.y, acc.y);
    acc.z = fmaf(w2, x2.z, acc.z); acc.w = fmaf(w2, x2.w, acc.w);
    acc.x = fmaf(w3, x3.x, acc.x); acc.y = fmaf(w3, x3.y, acc.y);
    acc.z = fmaf(w3, x3.z, acc.z); acc.w = fmaf(w3, x3.w, acc.w);
    acc.x = fmaf(w4, x4.x, acc.x); acc.y = fmaf(w4, x4.y, acc.y);
    acc.z = fmaf(w4, x4.z, acc.z); acc.w = fmaf(w4, x4.w, acc.w);
    acc.x = fmaf(w5, x5.x, acc.x); acc.y = fmaf(w5, x5.y, acc.y);
    acc.z = fmaf(w5, x5.z, acc.z); acc.w = fmaf(w5, x5.w, acc.w);
    acc.x = fmaf(w6, x6.x, acc.x); acc.y = fmaf(w6, x6.y, acc.y);
    acc.z = fmaf(w6, x6.z, acc.z); acc.w = fmaf(w6, x6.w, acc.w);
    acc.x = fmaf(w7, x7.x, acc.x); acc.y = fmaf(w7, x7.y, acc.y);
    acc.z = fmaf(w7, x7.z, acc.z); acc.w = fmaf(w7, x7.w, acc.w);

    // Write-through store: bursty DRAM writes, no L2 dirty-eviction
    // interleaving with the read-fill stream.
    __stwt(out + (size_t)bt * V4 + v4, acc);
}

extern "C" void kernel_launch(void* const* d_in, const int* in_sizes, int n_in,
                              void* d_out, int out_size) {
    const float4* x    = (const float4*)d_in[0];
    const float*  w    = (const float*)d_in[1];
    const float*  bias = (const float*)d_in[2];
    float4*       out  = (float4*)d_out;

    dim3 block(NTHR);
    dim3 grid((V4 + NTHR - 1) / NTHR, BT);   // (32, 1024)
    tokentree_kernel<<<grid, block>>>(x, w, bias, out);
}